// round 15
// baseline (speedup 1.0000x reference)
#include <cuda_runtime.h>
#include <cuda_fp16.h>
#include <cstdint>

#define T_TOK 36864

// ---------------- scratch ----------------
__device__ __align__(16) float g_big[56623104];        // [T][1536] fp32: x | o3_att | o7_att
__device__ __align__(16) float g_qkv[56623104];        // [T][1536] fp32: q | k | v
__device__ __align__(16) __half g_ah[18874368];        // o3/o7 fp16 [T][512]
__device__ __align__(16) __half g_whall[2359296];      // w1|qkv|w2|w3 (single fp16)
__device__ __align__(16) float g_bqkv[1536];
__device__ __align__(16) float g_ps[2097152];
__device__ __align__(16) float g_pq[2097152];
__device__ float g_mean[1536];
__device__ float g_var[1536];
__device__ __align__(16) float g_scale[1536];
__device__ __align__(16) float g_shift[1536];

#define OFF_W1   0u
#define OFF_QKV  262144u
#define OFF_W2   1048576u
#define OFF_W3   1572864u

__device__ __forceinline__ uint32_t smem_u32(const void* p) {
    uint32_t a;
    asm("{ .reg .u64 t; cvta.to.shared.u64 t, %1; cvt.u32.u64 %0, t; }" : "=r"(a) : "l"(p));
    return a;
}
#define LDM4(r, addr)                                                              \
    asm volatile("ldmatrix.sync.aligned.m8n8.x4.shared.b16 {%0,%1,%2,%3}, [%4];"   \
        : "=r"((r)[0]), "=r"((r)[1]), "=r"((r)[2]), "=r"((r)[3]) : "r"(addr))
#define CPA(d, s)   asm volatile("cp.async.cg.shared.global [%0], [%1], 16;" :: "r"(d), "l"(s))
#define CPCOMMIT()  asm volatile("cp.async.commit_group;" ::: "memory")
#define CPWAIT2()   asm volatile("cp.async.wait_group 2;" ::: "memory")

__device__ __forceinline__ void mma_f16(float* c, const uint32_t* a, const uint32_t* b) {
    asm volatile("mma.sync.aligned.m16n8k16.row.col.f32.f16.f16.f32 "
        "{%0,%1,%2,%3}, {%4,%5,%6,%7}, {%8,%9}, {%0,%1,%2,%3};"
        : "+f"(c[0]), "+f"(c[1]), "+f"(c[2]), "+f"(c[3])
        : "r"(a[0]), "r"(a[1]), "r"(a[2]), "r"(a[3]), "r"(b[0]), "r"(b[1]));
}

// ---------------------------------------------------------------------------
// prep: [0,4096): transpose x -> g_big cols 0-511 + per-batch stats partials
//       [4096,4672): all weights fp32 -> single fp16
//       [4672,4675): concat q/k/v bias
__global__ void prep(const float* __restrict__ x,
                     const float* __restrict__ w1, const float* __restrict__ qw,
                     const float* __restrict__ kw, const float* __restrict__ vw,
                     const float* __restrict__ w2, const float* __restrict__ w3,
                     const float* __restrict__ qb, const float* __restrict__ kb,
                     const float* __restrict__ vb) {
    const int blk = blockIdx.x, tid = threadIdx.x;
    if (blk < 4096) {
        __shared__ float s[4608];
        const float* xp = x + (size_t)blk * 4608;
#pragma unroll
        for (int i = tid; i < 4608; i += 512) s[i] = xp[i];
        __syncthreads();
        float sum = 0.f, sq = 0.f;
#pragma unroll
        for (int hw = 0; hw < 9; hw++) {
            float v = s[tid * 9 + hw];
            g_big[((size_t)blk * 9 + hw) * 1536 + tid] = v;
            sum += v;
            sq += v * v;
        }
        g_ps[(size_t)blk * 512 + tid] = sum;
        g_pq[(size_t)blk * 512 + tid] = sq;
    } else if (blk < 4672) {
        uint32_t i8 = (uint32_t)(blk - 4096) * 4096u + (uint32_t)tid * 8u;
        const float* src;
        uint32_t seg;
        if      (i8 <  262144u) { src = w1; seg = 0u; }
        else if (i8 <  524288u) { src = qw; seg = 262144u; }
        else if (i8 <  786432u) { src = kw; seg = 524288u; }
        else if (i8 < 1048576u) { src = vw; seg = 786432u; }
        else if (i8 < 1572864u) { src = w2; seg = 1048576u; }
        else                    { src = w3; seg = 1572864u; }
        const float* p = src + (i8 - seg);
        float v[8];
        *(float4*)v       = *(const float4*)p;
        *(float4*)(v + 4) = *(const float4*)(p + 4);
        uint4 H;
        uint32_t* hp = &H.x;
#pragma unroll
        for (int i = 0; i < 4; i++) {
            __half2 h = __floats2half2_rn(v[2 * i], v[2 * i + 1]);
            hp[i] = *(uint32_t*)&h;
        }
        *(uint4*)(g_whall + i8) = H;
    } else {
        int i = (blk - 4672) * 512 + tid;
        float v;
        if (i < 512) v = qb[i];
        else if (i < 1024) v = kb[i - 512];
        else v = vb[i - 1024];
        g_bqkv[i] = v;
    }
}

// finalize mean/var for 512 channels at coff from nparts partials
__global__ void stats_fin(int coff, int nparts) {
    __shared__ float rs[8][32], rq[8][32];
    int lane = threadIdx.x & 31, rp = threadIdx.x >> 5;
    int j = blockIdx.x * 32 + lane;
    float s = 0.f, q = 0.f;
    for (int r = rp; r < nparts; r += 8) {
        s += g_ps[(size_t)r * 512 + j];
        q += g_pq[(size_t)r * 512 + j];
    }
    rs[rp][lane] = s;
    rq[rp][lane] = q;
    __syncthreads();
    if (rp == 0) {
#pragma unroll
        for (int r = 1; r < 8; r++) { s += rs[r][lane]; q += rq[r][lane]; }
        float m = s / (float)T_TOK;
        g_mean[coff + j] = m;
        g_var[coff + j] = q / (float)T_TOK - m * m;
    }
}

// fold BN params into per-channel scale/shift over cols [0, n)
__global__ void scaleshift(const float* __restrict__ gam, const float* __restrict__ bet, int n) {
    int i = blockIdx.x * 256 + threadIdx.x;
    if (i < n) {
        float sc = gam[i] * rsqrtf(g_var[i] + 1e-5f);
        g_scale[i] = sc;
        g_shift[i] = bet[i] - g_mean[i] * sc;
    }
}

// ---------------------------------------------------------------------------
// out[t,m] = sum_k A[t,k]*W[m,k] + bias[m]; fp16 single-pass A.
// Block 128 tok x 128 ch, 8 warps (2x4), warp 64x32, k16 4-stage pipeline
// (compile-time buffer offsets via x4 unroll, wait_group 2), 2 CTA/SM.
// FUSE=1: A fp32 g_big (stride 1536); BN+relu+fp16 in fill, reg prefetch d=2.
// FUSE=0: A = fp16 g_ah [T][512] via cp.async.
// OM: 0 = fp16-round out to g_ah; 1 = fp32 [T][1536]; 2 = fp32 [B,512,3,3]
#define PITCH 48
#define WOFF  6144u
#define BUFSZ 12288u
template<int OM, bool FUSE>
__global__ __launch_bounds__(256, 2)
void mma_gemm(const float* __restrict__ Af, const __half* __restrict__ Ah,
              const __half* __restrict__ W,
              const int K, const float* __restrict__ bias, float* __restrict__ out) {
    extern __shared__ char smem[];
    const uint32_t sb = smem_u32(smem);
    const int tid = threadIdx.x;
    const int wid = tid >> 5, lane = tid & 31;
    const int warp_m = wid & 1, warp_n = wid >> 1;
    const int t0 = blockIdx.x * 128;
    const int m0 = blockIdx.y * 128;

    const int frow = tid >> 1, fh = tid & 1;
    const __half* gW = W + (size_t)(m0 + frow) * K + fh * 8;
    const uint32_t sdst = sb + frow * PITCH + fh * 16;

    const float* gAf = nullptr;
    const __half* gA_h = nullptr;
    if (FUSE) gAf = Af + (size_t)(t0 + frow) * 1536 + fh * 8;
    else      gA_h = Ah + (size_t)(t0 + frow) * K + fh * 8;

    const int lr = lane & 7, s = lane >> 3;
    const uint32_t aoff = sb + (uint32_t)(warp_m * 64 + lr + (s & 1) * 8) * PITCH + (s >> 1) * 16;
    const uint32_t woff = sb + WOFF + (uint32_t)(warp_n * 32 + lr + (s >> 1) * 8) * PITCH + (s & 1) * 16;

    float acc[4][4][4] = {};
    const int nc = K >> 4;   // multiple of 4 for all K used (512/1024/1536)

    float pa[2][8];
    // prologue: A-reg prefetch chunks 0,1 (FUSE) ; cp.async chunks 0,1,2 (3 groups)
    if (FUSE) {
        *(float4*)(pa[0])     = *(const float4*)gAf;
        *(float4*)(pa[0] + 4) = *(const float4*)(gAf + 4);
        *(float4*)(pa[1])     = *(const float4*)(gAf + 16);
        *(float4*)(pa[1] + 4) = *(const float4*)(gAf + 20);
    }
#pragma unroll
    for (int pc = 0; pc < 3; pc++) {
        const uint32_t nb = (uint32_t)pc * BUFSZ;
        if (!FUSE) CPA(sdst + nb, gA_h + pc * 16);
        CPA(sdst + nb + WOFF, gW + pc * 16);
        CPCOMMIT();
    }

    for (int c4 = 0; c4 < nc; c4 += 4) {
#pragma unroll
        for (int u = 0; u < 4; u++) {
            const int c = c4 + u;
            const uint32_t bb = (uint32_t)u * BUFSZ;   // compile-time
            if (FUSE) {
                // BN+relu+fp16 chunk c from pa[u&1] into buffer u
                // (pre-sync safe: buffer u last LDSM-read at chunk c-4)
                const int kc = (c << 4) + fh * 8;
                float sc[8], sh[8];
                *(float4*)sc       = *(const float4*)(g_scale + kc);
                *(float4*)(sc + 4) = *(const float4*)(g_scale + kc + 4);
                *(float4*)sh       = *(const float4*)(g_shift + kc);
                *(float4*)(sh + 4) = *(const float4*)(g_shift + kc + 4);
                uint4 H;
                uint32_t* hp = &H.x;
#pragma unroll
                for (int i = 0; i < 4; i++) {
                    float a0 = fmaxf(fmaf(pa[u & 1][2 * i],     sc[2 * i],     sh[2 * i]),     0.f);
                    float a1 = fmaxf(fmaf(pa[u & 1][2 * i + 1], sc[2 * i + 1], sh[2 * i + 1]), 0.f);
                    __half2 h = __floats2half2_rn(a0, a1);
                    hp[i] = *(uint32_t*)&h;
                }
                *(uint4*)(smem + (sdst - sb) + bb) = H;
                // A-reg prefetch chunk c+2 into the slot just consumed
                if (c + 2 < nc) {
                    const int kn = (c + 2) << 4;
                    *(float4*)(pa[u & 1])     = *(const float4*)(gAf + kn);
                    *(float4*)(pa[u & 1] + 4) = *(const float4*)(gAf + kn + 4);
                }
            }
            CPWAIT2();        // chunk c's copy complete (c+1, c+2 in flight)
            __syncthreads();
            if (c + 3 < nc) {
                const uint32_t nb = (uint32_t)((u + 3) & 3) * BUFSZ;
                const int kn = (c + 3) << 4;
                if (!FUSE) CPA(sdst + nb, gA_h + kn);
                CPA(sdst + nb + WOFF, gW + kn);
                CPCOMMIT();
            }

            uint32_t ah[4][4], w[4][2];
#pragma unroll
            for (int mt = 0; mt < 4; mt++)
                LDM4(ah[mt], aoff + bb + mt * (16 * PITCH));
#pragma unroll
            for (int p = 0; p < 2; p++) {
                uint32_t r[4];
                LDM4(r, woff + bb + p * (16 * PITCH));
                w[2 * p][0] = r[0]; w[2 * p][1] = r[1];
                w[2 * p + 1][0] = r[2]; w[2 * p + 1][1] = r[3];
            }
#pragma unroll
            for (int mt = 0; mt < 4; mt++)
#pragma unroll
                for (int nt = 0; nt < 4; nt++)
                    mma_f16(acc[mt][nt], ah[mt], w[nt]);
        }
    }

    // epilogue
    const int rl = lane >> 2, cl = (lane & 3) * 2;
#pragma unroll
    for (int nt = 0; nt < 4; nt++) {
        const int m = m0 + warp_n * 32 + nt * 8 + cl;
        const float b0 = bias[m], b1 = bias[m + 1];
#pragma unroll
        for (int mt = 0; mt < 4; mt++) {
            const int t = t0 + warp_m * 64 + mt * 16 + rl;
            float v00 = acc[mt][nt][0] + b0, v01 = acc[mt][nt][1] + b1;
            float v10 = acc[mt][nt][2] + b0, v11 = acc[mt][nt][3] + b1;
            if (OM == 0) {
                __half2 h0 = __floats2half2_rn(v00, v01);
                __half2 h1 = __floats2half2_rn(v10, v11);
                *(__half2*)(g_ah + (size_t)t * 512 + m) = h0;
                *(__half2*)(g_ah + (size_t)(t + 8) * 512 + m) = h1;
            } else if (OM == 1) {
                out[(size_t)t * 1536 + m] = v00;
                out[(size_t)t * 1536 + m + 1] = v01;
                out[(size_t)(t + 8) * 1536 + m] = v10;
                out[(size_t)(t + 8) * 1536 + m + 1] = v11;
            } else {
                int b = t / 9, hw = t - b * 9;
                out[((size_t)b * 512 + m) * 9 + hw] = v00;
                out[((size_t)b * 512 + m + 1) * 9 + hw] = v01;
                int b2 = (t + 8) / 9, hw2 = (t + 8) - b2 * 9;
                out[((size_t)b2 * 512 + m) * 9 + hw2] = v10;
                out[((size_t)b2 * 512 + m + 1) * 9 + hw2] = v11;
            }
        }
    }
}

// ---------------------------------------------------------------------------
// attention + fused output-stats partials. Block per (batch, head).
__global__ void attn_kernel(const float* __restrict__ relh,
                            const float* __restrict__ relw, int colOff) {
    int b = blockIdx.x >> 2;
    int h = blockIdx.x & 3;
    int d = threadIdx.x;  // 0..127
    __shared__ float sq[128][9], sk[128][9], sv[128][9], sp[128][9];
    __shared__ float sl[9][9];
    size_t tb = (size_t)b * 9;
    int ch = h * 128 + d;
    const float* qp = g_qkv + tb * 1536 + ch;
#pragma unroll
    for (int n = 0; n < 9; n++) {
        sq[d][n] = qp[n * 1536];
        sk[d][n] = qp[n * 1536 + 512];
        sv[d][n] = qp[n * 1536 + 1024];
    }
    float rw[3], rh2[3];
#pragma unroll
    for (int i = 0; i < 3; i++) { rw[i] = relw[ch * 3 + i]; rh2[i] = relh[ch * 3 + i]; }
#pragma unroll
    for (int i = 0; i < 3; i++)
#pragma unroll
        for (int j = 0; j < 3; j++)
            sp[d][i * 3 + j] = rw[i] + rh2[j];
    __syncthreads();
    if (d < 81) {
        int n = d / 9, mm = d % 9;
        float a = 0.f;
#pragma unroll 4
        for (int dd = 0; dd < 128; dd++)
            a += sq[dd][n] * sk[dd][mm] + sp[dd][n] * sq[dd][mm];
        sl[n][mm] = a;
    }
    __syncthreads();
    if (d < 9) {
        float mx = sl[d][0];
#pragma unroll
        for (int mm = 1; mm < 9; mm++) mx = fmaxf(mx, sl[d][mm]);
        float e[9], sum = 0.f;
#pragma unroll
        for (int mm = 0; mm < 9; mm++) { e[mm] = __expf(sl[d][mm] - mx); sum += e[mm]; }
        float inv = 1.f / sum;
#pragma unroll
        for (int mm = 0; mm < 9; mm++) sl[d][mm] = e[mm] * inv;
    }
    __syncthreads();
    float* op = g_big + tb * 1536 + colOff + ch;
    float psum = 0.f, psq = 0.f;
#pragma unroll
    for (int n = 0; n < 9; n++) {
        float a = 0.f;
#pragma unroll
        for (int mm = 0; mm < 9; mm++) a = fmaf(sv[d][mm], sl[n][mm], a);
        op[(size_t)n * 1536] = a;
        psum += a;
        psq += a * a;
    }
    g_ps[(size_t)b * 512 + ch] = psum;
    g_pq[(size_t)b * 512 + ch] = psq;
}

// ---------------------------------------------------------------------------
extern "C" void kernel_launch(void* const* d_in, const int* in_sizes, int n_in,
                              void* d_out, int out_size) {
    const float* x     = (const float*)d_in[0];
    const float* bn1_g = (const float*)d_in[1];
    const float* bn1_b = (const float*)d_in[2];
    const float* w1    = (const float*)d_in[3];
    const float* b1    = (const float*)d_in[4];
    const float* q_w   = (const float*)d_in[5];
    const float* q_b   = (const float*)d_in[6];
    const float* k_w   = (const float*)d_in[7];
    const float* k_b   = (const float*)d_in[8];
    const float* v_w   = (const float*)d_in[9];
    const float* v_b   = (const float*)d_in[10];
    const float* rel_h = (const float*)d_in[11];
    const float* rel_w = (const float*)d_in[12];
    const float* bn2_g = (const float*)d_in[13];
    const float* bn2_b = (const float*)d_in[14];
    const float* w2    = (const float*)d_in[15];
    const float* b2    = (const float*)d_in[16];
    const float* bn3_g = (const float*)d_in[17];
    const float* bn3_b = (const float*)d_in[18];
    const float* w3    = (const float*)d_in[19];
    const float* b3    = (const float*)d_in[20];

    __half *ah, *wh;
    float *big, *qkv, *bqkv;
    cudaGetSymbolAddress((void**)&big, g_big);
    cudaGetSymbolAddress((void**)&ah, g_ah);
    cudaGetSymbolAddress((void**)&wh, g_whall);
    cudaGetSymbolAddress((void**)&qkv, g_qkv);
    cudaGetSymbolAddress((void**)&bqkv, g_bqkv);

    const int SMB = 4 * BUFSZ;  // 49152 (4-stage)
    cudaFuncSetAttribute(mma_gemm<0, true >, cudaFuncAttributeMaxDynamicSharedMemorySize, SMB);
    cudaFuncSetAttribute(mma_gemm<1, false>, cudaFuncAttributeMaxDynamicSharedMemorySize, SMB);
    cudaFuncSetAttribute(mma_gemm<2, true >, cudaFuncAttributeMaxDynamicSharedMemorySize, SMB);

    dim3 g4(288, 4), g12(288, 12);

    prep<<<4675, 512>>>(x, w1, q_w, k_w, v_w, w2, w3, q_b, k_b, v_b);
    stats_fin<<<16, 256>>>(0, 4096);
    scaleshift<<<2, 256>>>(bn1_g, bn1_b, 512);
    mma_gemm<0, true ><<<g4, 256, SMB>>>(big, nullptr, wh + OFF_W1, 512, b1, nullptr);
    mma_gemm<1, false><<<g12, 256, SMB>>>(nullptr, ah, wh + OFF_QKV, 512, bqkv, qkv);
    attn_kernel<<<16384, 128>>>(rel_h, rel_w, 512);
    stats_fin<<<16, 256>>>(512, 4096);
    scaleshift<<<4, 256>>>(bn2_g, bn2_b, 1024);
    mma_gemm<0, true ><<<g4, 256, SMB>>>(big, nullptr, wh + OFF_W2, 1024, b2, nullptr);
    mma_gemm<1, false><<<g12, 256, SMB>>>(nullptr, ah, wh + OFF_QKV, 512, bqkv, qkv);
    attn_kernel<<<16384, 128>>>(rel_h, rel_w, 1024);
    stats_fin<<<16, 256>>>(1024, 4096);
    scaleshift<<<6, 256>>>(bn3_g, bn3_b, 1536);
    mma_gemm<2, true ><<<g4, 256, SMB>>>(big, nullptr, wh + OFF_W3, 1536, b3, (float*)d_out);
}

// round 16
// speedup vs baseline: 1.0235x; 1.0235x over previous
#include <cuda_runtime.h>
#include <cuda_fp16.h>
#include <cstdint>

#define T_TOK 36864

// ---------------- scratch ----------------
__device__ __align__(16) float g_big[56623104];        // [T][1536] fp32: x | o3_att | o7_att
__device__ __align__(16) float g_qkv[56623104];        // [T][1536] fp32: q | k | v
__device__ __align__(16) __half g_ah[18874368];        // o3/o7 fp16 [T][512]
__device__ __align__(16) __half g_whall[2359296];      // w1|qkv|w2|w3 (single fp16)
__device__ __align__(16) float g_bqkv[1536];
__device__ __align__(16) float g_ps[2097152];
__device__ __align__(16) float g_pq[2097152];
__device__ float g_mean[1536];
__device__ float g_var[1536];
__device__ __align__(16) float g_scale[1536];
__device__ __align__(16) float g_shift[1536];

#define OFF_W1   0u
#define OFF_QKV  262144u
#define OFF_W2   1048576u
#define OFF_W3   1572864u

__device__ __forceinline__ uint32_t smem_u32(const void* p) {
    uint32_t a;
    asm("{ .reg .u64 t; cvta.to.shared.u64 t, %1; cvt.u32.u64 %0, t; }" : "=r"(a) : "l"(p));
    return a;
}
#define LDM4(r, addr)                                                              \
    asm volatile("ldmatrix.sync.aligned.m8n8.x4.shared.b16 {%0,%1,%2,%3}, [%4];"   \
        : "=r"((r)[0]), "=r"((r)[1]), "=r"((r)[2]), "=r"((r)[3]) : "r"(addr))
#define CPA(d, s)   asm volatile("cp.async.cg.shared.global [%0], [%1], 16;" :: "r"(d), "l"(s))
#define CPCOMMIT()  asm volatile("cp.async.commit_group;" ::: "memory")
#define CPWAIT0()   asm volatile("cp.async.wait_group 0;" ::: "memory")

__device__ __forceinline__ void mma_f16(float* c, const uint32_t* a, const uint32_t* b) {
    asm volatile("mma.sync.aligned.m16n8k16.row.col.f32.f16.f16.f32 "
        "{%0,%1,%2,%3}, {%4,%5,%6,%7}, {%8,%9}, {%0,%1,%2,%3};"
        : "+f"(c[0]), "+f"(c[1]), "+f"(c[2]), "+f"(c[3])
        : "r"(a[0]), "r"(a[1]), "r"(a[2]), "r"(a[3]), "r"(b[0]), "r"(b[1]));
}

// ---------------------------------------------------------------------------
// prep: [0,4096): transpose x -> g_big cols 0-511 + per-batch stats partials
//       [4096,4672): all weights fp32 -> single fp16
//       [4672,4675): concat q/k/v bias
__global__ void prep(const float* __restrict__ x,
                     const float* __restrict__ w1, const float* __restrict__ qw,
                     const float* __restrict__ kw, const float* __restrict__ vw,
                     const float* __restrict__ w2, const float* __restrict__ w3,
                     const float* __restrict__ qb, const float* __restrict__ kb,
                     const float* __restrict__ vb) {
    const int blk = blockIdx.x, tid = threadIdx.x;
    if (blk < 4096) {
        __shared__ float s[4608];
        const float* xp = x + (size_t)blk * 4608;
#pragma unroll
        for (int i = tid; i < 4608; i += 512) s[i] = xp[i];
        __syncthreads();
        float sum = 0.f, sq = 0.f;
#pragma unroll
        for (int hw = 0; hw < 9; hw++) {
            float v = s[tid * 9 + hw];
            g_big[((size_t)blk * 9 + hw) * 1536 + tid] = v;
            sum += v;
            sq += v * v;
        }
        g_ps[(size_t)blk * 512 + tid] = sum;
        g_pq[(size_t)blk * 512 + tid] = sq;
    } else if (blk < 4672) {
        uint32_t i8 = (uint32_t)(blk - 4096) * 4096u + (uint32_t)tid * 8u;
        const float* src;
        uint32_t seg;
        if      (i8 <  262144u) { src = w1; seg = 0u; }
        else if (i8 <  524288u) { src = qw; seg = 262144u; }
        else if (i8 <  786432u) { src = kw; seg = 524288u; }
        else if (i8 < 1048576u) { src = vw; seg = 786432u; }
        else if (i8 < 1572864u) { src = w2; seg = 1048576u; }
        else                    { src = w3; seg = 1572864u; }
        const float* p = src + (i8 - seg);
        float v[8];
        *(float4*)v       = *(const float4*)p;
        *(float4*)(v + 4) = *(const float4*)(p + 4);
        uint4 H;
        uint32_t* hp = &H.x;
#pragma unroll
        for (int i = 0; i < 4; i++) {
            __half2 h = __floats2half2_rn(v[2 * i], v[2 * i + 1]);
            hp[i] = *(uint32_t*)&h;
        }
        *(uint4*)(g_whall + i8) = H;
    } else {
        int i = (blk - 4672) * 512 + tid;
        float v;
        if (i < 512) v = qb[i];
        else if (i < 1024) v = kb[i - 512];
        else v = vb[i - 1024];
        g_bqkv[i] = v;
    }
}

// ---------------------------------------------------------------------------
// merged stats finalize + BN fold. Block j covers cols [j*32, j*32+32).
// cols >= coff: reduce nparts partials -> mean/var, then scale/shift.
// cols <  coff: mean/var already valid; recompute scale/shift (new gamma/beta).
__global__ void stats_sc(int coff, int nparts,
                         const float* __restrict__ gam, const float* __restrict__ bet) {
    __shared__ float rs[8][32], rq[8][32];
    const int lane = threadIdx.x & 31, rp = threadIdx.x >> 5;
    const int col = blockIdx.x * 32 + lane;
    if (col >= coff) {
        const int j = col - coff;
        float s = 0.f, q = 0.f;
        for (int r = rp; r < nparts; r += 8) {
            s += g_ps[(size_t)r * 512 + j];
            q += g_pq[(size_t)r * 512 + j];
        }
        rs[rp][lane] = s;
        rq[rp][lane] = q;
        __syncthreads();
        if (rp == 0) {
#pragma unroll
            for (int r = 1; r < 8; r++) { s += rs[r][lane]; q += rq[r][lane]; }
            float m = s / (float)T_TOK;
            float v = q / (float)T_TOK - m * m;
            g_mean[col] = m;
            g_var[col] = v;
            float sc = gam[col] * rsqrtf(v + 1e-5f);
            g_scale[col] = sc;
            g_shift[col] = bet[col] - m * sc;
        }
    } else if (rp == 0) {
        float m = g_mean[col];
        float sc = gam[col] * rsqrtf(g_var[col] + 1e-5f);
        g_scale[col] = sc;
        g_shift[col] = bet[col] - m * sc;
    }
}

// ---------------------------------------------------------------------------
// out[t,m] = sum_k A[t,k]*W[m,k] + bias[m]; fp16 single-pass A everywhere.
// Block 128 tok x 128 ch, 8 warps (2x4), warp 64x32, k16 2-stage, 2 CTA/SM.
// FUSE=1: A fp32 g_big (stride 1536); BN+relu+round-fp16 in fill (reg prefetch).
// FUSE=0: A = fp16 g_ah [T][512] via cp.async.
// OM: 0 = fp16-round out to g_ah; 1 = fp32 [T][1536]; 2 = fp32 [B,512,3,3]
#define PITCH 48
#define WOFF  6144u
#define BUFSZ 12288u
template<int OM, bool FUSE>
__global__ __launch_bounds__(256, 2)
void mma_gemm(const float* __restrict__ Af, const __half* __restrict__ Ah,
              const __half* __restrict__ W,
              const int K, const float* __restrict__ bias, float* __restrict__ out) {
    extern __shared__ char smem[];
    const uint32_t sb = smem_u32(smem);
    const int tid = threadIdx.x;
    const int wid = tid >> 5, lane = tid & 31;
    const int warp_m = wid & 1, warp_n = wid >> 1;
    const int t0 = blockIdx.x * 128;
    const int m0 = blockIdx.y * 128;

    const int frow = tid >> 1, fh = tid & 1;
    const __half* gW = W + (size_t)(m0 + frow) * K + fh * 8;
    const uint32_t sdst = sb + frow * PITCH + fh * 16;

    const float* gAf = nullptr;
    const __half* gA_h = nullptr;
    if (FUSE) gAf = Af + (size_t)(t0 + frow) * 1536 + fh * 8;
    else      gA_h = Ah + (size_t)(t0 + frow) * K + fh * 8;

    const int lr = lane & 7, s = lane >> 3;
    const uint32_t aoff = sb + (uint32_t)(warp_m * 64 + lr + (s & 1) * 8) * PITCH + (s >> 1) * 16;
    const uint32_t woff = sb + WOFF + (uint32_t)(warp_n * 32 + lr + (s >> 1) * 8) * PITCH + (s & 1) * 16;

    float acc[4][4][4] = {};
    const int nc = K >> 4;

    float pa[8];
    // prologue
    if (FUSE) {
        *(float4*)pa       = *(const float4*)gAf;
        *(float4*)(pa + 4) = *(const float4*)(gAf + 4);
    } else {
        CPA(sdst, gA_h);
    }
    CPA(sdst + WOFF, gW);
    CPCOMMIT();

    for (int c = 0; c < nc; c++) {
        const uint32_t bb = (c & 1) * BUFSZ;
        if (FUSE) {
            // BN+relu+fp16-round chunk c from pa into this chunk's buffer
            // (pre-sync safe: buffer bb last read by compute c-2)
            const int kc = (c << 4) + fh * 8;
            float sc[8], sh[8];
            *(float4*)sc       = *(const float4*)(g_scale + kc);
            *(float4*)(sc + 4) = *(const float4*)(g_scale + kc + 4);
            *(float4*)sh       = *(const float4*)(g_shift + kc);
            *(float4*)(sh + 4) = *(const float4*)(g_shift + kc + 4);
            uint4 H;
            uint32_t* hp = &H.x;
#pragma unroll
            for (int i = 0; i < 4; i++) {
                float a0 = fmaxf(fmaf(pa[2 * i],     sc[2 * i],     sh[2 * i]),     0.f);
                float a1 = fmaxf(fmaf(pa[2 * i + 1], sc[2 * i + 1], sh[2 * i + 1]), 0.f);
                __half2 h = __floats2half2_rn(a0, a1);
                hp[i] = *(uint32_t*)&h;
            }
            *(uint4*)(smem + (sdst - sb) + bb) = H;
        }
        CPWAIT0();
        __syncthreads();
        if (c + 1 < nc) {
            const uint32_t nb = ((c + 1) & 1) * BUFSZ;
            const int kn = (c + 1) << 4;
            if (FUSE) {
                *(float4*)pa       = *(const float4*)(gAf + kn);
                *(float4*)(pa + 4) = *(const float4*)(gAf + kn + 4);
            } else {
                CPA(sdst + nb, gA_h + kn);
            }
            CPA(sdst + nb + WOFF, gW + kn);
            CPCOMMIT();
        }

        uint32_t ah[4][4], w[4][2];
#pragma unroll
        for (int mt = 0; mt < 4; mt++)
            LDM4(ah[mt], aoff + bb + mt * (16 * PITCH));
#pragma unroll
        for (int p = 0; p < 2; p++) {
            uint32_t r[4];
            LDM4(r, woff + bb + p * (16 * PITCH));
            w[2 * p][0] = r[0]; w[2 * p][1] = r[1];
            w[2 * p + 1][0] = r[2]; w[2 * p + 1][1] = r[3];
        }
#pragma unroll
        for (int mt = 0; mt < 4; mt++)
#pragma unroll
            for (int nt = 0; nt < 4; nt++)
                mma_f16(acc[mt][nt], ah[mt], w[nt]);
    }

    // epilogue
    const int rl = lane >> 2, cl = (lane & 3) * 2;
#pragma unroll
    for (int nt = 0; nt < 4; nt++) {
        const int m = m0 + warp_n * 32 + nt * 8 + cl;
        const float b0 = bias[m], b1 = bias[m + 1];
#pragma unroll
        for (int mt = 0; mt < 4; mt++) {
            const int t = t0 + warp_m * 64 + mt * 16 + rl;
            float v00 = acc[mt][nt][0] + b0, v01 = acc[mt][nt][1] + b1;
            float v10 = acc[mt][nt][2] + b0, v11 = acc[mt][nt][3] + b1;
            if (OM == 0) {
                __half2 h0 = __floats2half2_rn(v00, v01);
                __half2 h1 = __floats2half2_rn(v10, v11);
                *(__half2*)(g_ah + (size_t)t * 512 + m) = h0;
                *(__half2*)(g_ah + (size_t)(t + 8) * 512 + m) = h1;
            } else if (OM == 1) {
                out[(size_t)t * 1536 + m] = v00;
                out[(size_t)t * 1536 + m + 1] = v01;
                out[(size_t)(t + 8) * 1536 + m] = v10;
                out[(size_t)(t + 8) * 1536 + m + 1] = v11;
            } else {
                int b = t / 9, hw = t - b * 9;
                out[((size_t)b * 512 + m) * 9 + hw] = v00;
                out[((size_t)b * 512 + m + 1) * 9 + hw] = v01;
                int b2 = (t + 8) / 9, hw2 = (t + 8) - b2 * 9;
                out[((size_t)b2 * 512 + m) * 9 + hw2] = v10;
                out[((size_t)b2 * 512 + m + 1) * 9 + hw2] = v11;
            }
        }
    }
}

// ---------------------------------------------------------------------------
// attention + fused output-stats partials. Block per (batch, head).
__global__ void attn_kernel(const float* __restrict__ relh,
                            const float* __restrict__ relw, int colOff) {
    int b = blockIdx.x >> 2;
    int h = blockIdx.x & 3;
    int d = threadIdx.x;  // 0..127
    __shared__ float sq[128][9], sk[128][9], sv[128][9], sp[128][9];
    __shared__ float sl[9][9];
    size_t tb = (size_t)b * 9;
    int ch = h * 128 + d;
    const float* qp = g_qkv + tb * 1536 + ch;
#pragma unroll
    for (int n = 0; n < 9; n++) {
        sq[d][n] = qp[n * 1536];
        sk[d][n] = qp[n * 1536 + 512];
        sv[d][n] = qp[n * 1536 + 1024];
    }
    float rw[3], rh2[3];
#pragma unroll
    for (int i = 0; i < 3; i++) { rw[i] = relw[ch * 3 + i]; rh2[i] = relh[ch * 3 + i]; }
#pragma unroll
    for (int i = 0; i < 3; i++)
#pragma unroll
        for (int j = 0; j < 3; j++)
            sp[d][i * 3 + j] = rw[i] + rh2[j];
    __syncthreads();
    if (d < 81) {
        int n = d / 9, mm = d % 9;
        float a = 0.f;
#pragma unroll 4
        for (int dd = 0; dd < 128; dd++)
            a += sq[dd][n] * sk[dd][mm] + sp[dd][n] * sq[dd][mm];
        sl[n][mm] = a;
    }
    __syncthreads();
    if (d < 9) {
        float mx = sl[d][0];
#pragma unroll
        for (int mm = 1; mm < 9; mm++) mx = fmaxf(mx, sl[d][mm]);
        float e[9], sum = 0.f;
#pragma unroll
        for (int mm = 0; mm < 9; mm++) { e[mm] = __expf(sl[d][mm] - mx); sum += e[mm]; }
        float inv = 1.f / sum;
#pragma unroll
        for (int mm = 0; mm < 9; mm++) sl[d][mm] = e[mm] * inv;
    }
    __syncthreads();
    float* op = g_big + tb * 1536 + colOff + ch;
    float psum = 0.f, psq = 0.f;
#pragma unroll
    for (int n = 0; n < 9; n++) {
        float a = 0.f;
#pragma unroll
        for (int mm = 0; mm < 9; mm++) a = fmaf(sv[d][mm], sl[n][mm], a);
        op[(size_t)n * 1536] = a;
        psum += a;
        psq += a * a;
    }
    g_ps[(size_t)b * 512 + ch] = psum;
    g_pq[(size_t)b * 512 + ch] = psq;
}

// ---------------------------------------------------------------------------
extern "C" void kernel_launch(void* const* d_in, const int* in_sizes, int n_in,
                              void* d_out, int out_size) {
    const float* x     = (const float*)d_in[0];
    const float* bn1_g = (const float*)d_in[1];
    const float* bn1_b = (const float*)d_in[2];
    const float* w1    = (const float*)d_in[3];
    const float* b1    = (const float*)d_in[4];
    const float* q_w   = (const float*)d_in[5];
    const float* q_b   = (const float*)d_in[6];
    const float* k_w   = (const float*)d_in[7];
    const float* k_b   = (const float*)d_in[8];
    const float* v_w   = (const float*)d_in[9];
    const float* v_b   = (const float*)d_in[10];
    const float* rel_h = (const float*)d_in[11];
    const float* rel_w = (const float*)d_in[12];
    const float* bn2_g = (const float*)d_in[13];
    const float* bn2_b = (const float*)d_in[14];
    const float* w2    = (const float*)d_in[15];
    const float* b2    = (const float*)d_in[16];
    const float* bn3_g = (const float*)d_in[17];
    const float* bn3_b = (const float*)d_in[18];
    const float* w3    = (const float*)d_in[19];
    const float* b3    = (const float*)d_in[20];

    __half *ah, *wh;
    float *big, *qkv, *bqkv;
    cudaGetSymbolAddress((void**)&big, g_big);
    cudaGetSymbolAddress((void**)&ah, g_ah);
    cudaGetSymbolAddress((void**)&wh, g_whall);
    cudaGetSymbolAddress((void**)&qkv, g_qkv);
    cudaGetSymbolAddress((void**)&bqkv, g_bqkv);

    const int SMB = 2 * BUFSZ;  // 24576
    cudaFuncSetAttribute(mma_gemm<0, true >, cudaFuncAttributeMaxDynamicSharedMemorySize, SMB);
    cudaFuncSetAttribute(mma_gemm<1, false>, cudaFuncAttributeMaxDynamicSharedMemorySize, SMB);
    cudaFuncSetAttribute(mma_gemm<2, true >, cudaFuncAttributeMaxDynamicSharedMemorySize, SMB);

    dim3 g4(288, 4), g12(288, 12);

    prep<<<4675, 512>>>(x, w1, q_w, k_w, v_w, w2, w3, q_b, k_b, v_b);
    stats_sc<<<16, 256>>>(0, 4096, bn1_g, bn1_b);
    mma_gemm<0, true ><<<g4, 256, SMB>>>(big, nullptr, wh + OFF_W1, 512, b1, nullptr);
    mma_gemm<1, false><<<g12, 256, SMB>>>(nullptr, ah, wh + OFF_QKV, 512, bqkv, qkv);
    attn_kernel<<<16384, 128>>>(rel_h, rel_w, 512);
    stats_sc<<<32, 256>>>(512, 4096, bn2_g, bn2_b);
    mma_gemm<0, true ><<<g4, 256, SMB>>>(big, nullptr, wh + OFF_W2, 1024, b2, nullptr);
    mma_gemm<1, false><<<g12, 256, SMB>>>(nullptr, ah, wh + OFF_QKV, 512, bqkv, qkv);
    attn_kernel<<<16384, 128>>>(rel_h, rel_w, 1024);
    stats_sc<<<48, 256>>>(1024, 4096, bn3_g, bn3_b);
    mma_gemm<2, true ><<<g4, 256, SMB>>>(big, nullptr, wh + OFF_W3, 1536, b3, (float*)d_out);
}